// round 15
// baseline (speedup 1.0000x reference)
#include <cuda_runtime.h>
#include <cuda_fp16.h>
#include <cstdint>

// ---------------------------------------------------------------------------
// Problem constants
// ---------------------------------------------------------------------------
#define B_  32
#define D_  3
#define T_  16384
#define S_  128
#define L_  16
#define H_  512
#define C_  10
#define TP  16369          // T - L + 1 valid positions
#define SHN 48             // D*L = K (3 k-steps of 16)

#define NT      128        // positions per block tile (GEMM N-tile)
#define TPB     (T_ / NT)          // 128 tiles per batch
#define NTILES  (B_ * TPB)         // 4096
#define THR     256
#define GRID    296        // 2 blocks / SM
#define XT_W    (NT + L_)  // 144 elements per x row in tile
#define LD4     ((D_ * XT_W) / 4)  // 108 float4 loads per tile

#define INF_F __int_as_float(0x7F800000)

// per-batch completed-tile counters; monotonic (each launch adds exactly TPB)
__device__ unsigned int g_cnt[B_];

// ---------------------------------------------------------------------------
// D(16x8) += A(16x16,row) * B(16x8,col)   f16 x f16 -> f32
__device__ __forceinline__ void mma16(float* d, uint32_t a0, uint32_t a1,
                                      uint32_t a2, uint32_t a3,
                                      uint32_t b0, uint32_t b1) {
    asm volatile(
        "mma.sync.aligned.m16n8k16.row.col.f32.f16.f16.f32 "
        "{%0,%1,%2,%3}, {%4,%5,%6,%7}, {%8,%9}, {%0,%1,%2,%3};"
        : "+f"(d[0]), "+f"(d[1]), "+f"(d[2]), "+f"(d[3])
        : "r"(a0), "r"(a1), "r"(a2), "r"(a3), "r"(b0), "r"(b1));
}

__device__ __forceinline__ uint32_t packh2(float lo, float hi) {
    __half2 h = __floats2half2_rn(lo, hi);
    return *reinterpret_cast<uint32_t*>(&h);
}

// ---------------------------------------------------------------------------
// MLP for one batch — run by the last-finisher block. Lean + __noinline__.
// Reads distances via __ldcg (they live in L2 from atomicMin).
// ---------------------------------------------------------------------------
__device__ __noinline__ void mlp_tail(
    int b, const float* __restrict__ dist,
    const float* __restrict__ W1, const float* __restrict__ b1,
    const float* __restrict__ W2, const float* __restrict__ b2,
    float* __restrict__ out_cls, float* hs)
{
    const int tid  = threadIdx.x;    // 256 = 8 warps
    const int wid  = tid >> 5;
    const int lane = tid & 31;

    const float4 d4 = __ldcg(reinterpret_cast<const float4*>(dist + b * S_) + lane);

    // Layer 1: warp w -> neurons [w*64, w*64+64), 4 at a time (ILP shfls)
    for (int i = 0; i < 16; ++i) {
        float acc[4];
        #pragma unroll
        for (int j = 0; j < 4; ++j) {
            const int h = wid * 64 + i * 4 + j;
            const float4 w4 = __ldg(reinterpret_cast<const float4*>(W1 + h * S_) + lane);
            float a = d4.x * w4.x;
            a = fmaf(d4.y, w4.y, a);
            a = fmaf(d4.z, w4.z, a);
            a = fmaf(d4.w, w4.w, a);
            acc[j] = a;
        }
        #pragma unroll
        for (int off = 16; off > 0; off >>= 1)
            #pragma unroll
            for (int j = 0; j < 4; ++j)
                acc[j] += __shfl_xor_sync(0xffffffffu, acc[j], off);
        #pragma unroll
        for (int j = 0; j < 4; ++j)
            if (lane == j) {
                const int h = wid * 64 + i * 4 + j;
                hs[h] = fmaxf(acc[j] + b1[h], 0.f);
            }
    }
    __syncthreads();

    // Layer 2: classes round-robin over 8 warps
    for (int c = wid; c < C_; c += 8) {
        const float4* w4p = reinterpret_cast<const float4*>(W2 + c * H_);
        const float4* h4p = reinterpret_cast<const float4*>(hs);
        float acc = 0.f;
        #pragma unroll
        for (int jj = 0; jj < 4; ++jj) {
            const float4 w4 = __ldg(w4p + lane + jj * 32);
            const float4 h4 = h4p[lane + jj * 32];
            acc = fmaf(w4.x, h4.x, acc);
            acc = fmaf(w4.y, h4.y, acc);
            acc = fmaf(w4.z, h4.z, acc);
            acc = fmaf(w4.w, h4.w, acc);
        }
        #pragma unroll
        for (int off = 16; off > 0; off >>= 1)
            acc += __shfl_xor_sync(0xffffffffu, acc, off);
        if (lane == 0) out_cls[b * C_ + c] = acc + b2[c];
    }
    __syncthreads();   // hs reuse safety before block resumes dist loop
}

// ---------------------------------------------------------------------------
// Kernel: persistent fp16-MMA shapelet distance + last-finisher MLP
// ---------------------------------------------------------------------------
__global__ __launch_bounds__(THR, 2) void dist_kernel(
    const float* __restrict__ x,
    const float* __restrict__ shg,
    const float* __restrict__ W1,
    const float* __restrict__ b1,
    const float* __restrict__ W2,
    const float* __restrict__ b2,
    float* __restrict__ out_dist,
    float* __restrict__ out_cls)
{
    __shared__ __align__(16) float  xs[D_ * XT_W];   // raw fp32 (exact wsq)
    __shared__ __align__(16) __half hA[D_ * XT_W];   // hA[i] = f16(x[i])
    __shared__ __align__(16) __half hB[D_ * XT_W];   // hB[i] = f16(x[i+1] in-row)
    __shared__ __align__(16) float  swsq[NT];
    __shared__ __align__(16) float  hs[H_];          // MLP hidden (tail only)
    __shared__ float  sssq[S_];
    __shared__ int    sdmin[S_];
    __shared__ int    s_run;

    const int tid  = threadIdx.x;
    const int wid  = tid >> 5;
    const int lane = tid & 31;
    const int q    = lane >> 2;      // groupID
    const int r    = lane & 3;       // threadID_in_group

    const int mbase = (wid & 3) * 32;       // warp's 32 M-rows
    const int nbase = (wid >> 2) * 64;      // warp's 64 N-cols

    // --- one-time: exact fp32 shapelet squared norms; A fragments -> regs ---
    if (tid < S_) {
        const float* srow = shg + tid * SHN;
        float ssq = 0.f;
        #pragma unroll
        for (int k = 0; k < SHN; ++k) ssq = fmaf(srow[k], srow[k], ssq);
        sssq[tid] = ssq;
        sdmin[tid] = 0x7F800000;
    }

    // A fragments: afr[ks][mt][4]; tile-invariant
    uint32_t afr[3][2][4];
    #pragma unroll
    for (int ks = 0; ks < 3; ++ks) {
        #pragma unroll
        for (int mt = 0; mt < 2; ++mt) {
            const int r0 = mbase + mt * 16 + q;
            const int r1 = r0 + 8;
            const int k0 = ks * 16 + 2 * r;
            const float* p0 = shg + r0 * SHN + k0;
            const float* p1 = shg + r1 * SHN + k0;
            afr[ks][mt][0] = packh2(-2.f * p0[0], -2.f * p0[1]);
            afr[ks][mt][1] = packh2(-2.f * p1[0], -2.f * p1[1]);
            afr[ks][mt][2] = packh2(-2.f * p0[8], -2.f * p0[9]);
            afr[ks][mt][3] = packh2(-2.f * p1[8], -2.f * p1[9]);
        }
    }
    __syncthreads();

    const uint32_t* hA32 = reinterpret_cast<const uint32_t*>(hA);
    const uint32_t* hB32 = reinterpret_cast<const uint32_t*>(hB);
    const uint32_t* hw = (q & 1) ? hB32 : hA32;
    const int lane_off = q + 2 * r - (q & 1);

    for (int tile = blockIdx.x; tile < NTILES; tile += GRID) {
        const int b     = tile >> 7;                  // TPB = 128
        const int tbase = (tile & (TPB - 1)) * NT;
        const float* xb = x + (size_t)b * D_ * T_;

        // ---- phase 1: load x tile (fp32 + two fp16 copies), 108 float4 ----
        if (tid < LD4) {
            const int d = tid / (XT_W / 4);           // XT_W/4 = 36
            const int j = (tid % (XT_W / 4)) * 4;
            const int g = tbase + j;
            float4 v;
            if (g + 3 < T_) {
                v = *reinterpret_cast<const float4*>(xb + d * T_ + g);
            } else {
                v.x = (g     < T_) ? xb[d*T_ + g]     : 0.f;
                v.y = (g + 1 < T_) ? xb[d*T_ + g + 1] : 0.f;
                v.z = (g + 2 < T_) ? xb[d*T_ + g + 2] : 0.f;
                v.w = (g + 3 < T_) ? xb[d*T_ + g + 3] : 0.f;
            }
            *reinterpret_cast<float4*>(&xs[d * XT_W + j]) = v;
            const int hi = d * XT_W + j;
            *reinterpret_cast<uint32_t*>(&hA[hi])     = packh2(v.x, v.y);
            *reinterpret_cast<uint32_t*>(&hA[hi + 2]) = packh2(v.z, v.w);
            if (j > 0) hB[hi - 1] = __float2half(v.x);
            hB[hi    ] = __float2half(v.y);
            hB[hi + 1] = __float2half(v.z);
            hB[hi + 2] = __float2half(v.w);
        }
        __syncthreads();

        // ---- phase 2: wsq, one position per thread (tid < 128) ----
        if (tid < NT) {
            float w0 = 0.f, w1 = 0.f, w2 = 0.f;
            #pragma unroll
            for (int l = 0; l < L_; ++l) {
                const float v0 = xs[0 * XT_W + tid + l];
                const float v1 = xs[1 * XT_W + tid + l];
                const float v2 = xs[2 * XT_W + tid + l];
                w0 = fmaf(v0, v0, w0);
                w1 = fmaf(v1, v1, w1);
                w2 = fmaf(v2, v2, w2);
            }
            swsq[tid] = (tbase + tid < TP) ? (w0 + w1 + w2) : INF_F;
        }

        // ---- phase 3: MMA, warp tile 32M x 64N, K=48 (3 k-steps) ----
        float acc[2][8][4];
        #pragma unroll
        for (int mt = 0; mt < 2; ++mt)
            #pragma unroll
            for (int nt = 0; nt < 8; ++nt)
                #pragma unroll
                for (int e = 0; e < 4; ++e) acc[mt][nt][e] = 0.f;

        #pragma unroll
        for (int ks = 0; ks < 3; ++ks) {
            const int base = (ks * XT_W + nbase + lane_off) >> 1;
            #pragma unroll
            for (int nt = 0; nt < 8; ++nt) {
                const uint32_t b0 = hw[base + nt * 4];
                const uint32_t b1 = hw[base + nt * 4 + 4];
                mma16(acc[0][nt], afr[ks][0][0], afr[ks][0][1],
                                  afr[ks][0][2], afr[ks][0][3], b0, b1);
                mma16(acc[1][nt], afr[ks][1][0], afr[ks][1][1],
                                  afr[ks][1][2], afr[ks][1][3], b0, b1);
            }
        }
        __syncthreads();   // swsq ready

        // ---- phase 4: dist = min_n(acc + wsq[n]); smem atomic min ----
        float wq[8][2];
        #pragma unroll
        for (int nt = 0; nt < 8; ++nt) {
            wq[nt][0] = swsq[nbase + nt * 8 + r * 2    ];
            wq[nt][1] = swsq[nbase + nt * 8 + r * 2 + 1];
        }
        float rmin[2][2];
        #pragma unroll
        for (int mt = 0; mt < 2; ++mt)
            #pragma unroll
            for (int h = 0; h < 2; ++h) {
                float m = INF_F;
                #pragma unroll
                for (int nt = 0; nt < 8; ++nt) {
                    m = fminf(m, acc[mt][nt][h * 2    ] + wq[nt][0]);
                    m = fminf(m, acc[mt][nt][h * 2 + 1] + wq[nt][1]);
                }
                rmin[mt][h] = m;
            }
        #pragma unroll
        for (int mt = 0; mt < 2; ++mt)
            #pragma unroll
            for (int h = 0; h < 2; ++h) {
                float v = rmin[mt][h];
                v = fminf(v, __shfl_xor_sync(0xffffffffu, v, 1));
                v = fminf(v, __shfl_xor_sync(0xffffffffu, v, 2));
                rmin[mt][h] = v;
            }
        if (r == 0) {
            #pragma unroll
            for (int mt = 0; mt < 2; ++mt)
                #pragma unroll
                for (int h = 0; h < 2; ++h) {
                    const int row = mbase + mt * 16 + h * 8 + q;
                    const float v = rmin[mt][h] + sssq[row];
                    atomicMin(&sdmin[row], __float_as_int(v));
                }
        }
        __syncthreads();

        // ---- phase 5: fold into global; publish; last finisher runs MLP ----
        if (tid < S_) {
            const int v = sdmin[tid];
            atomicMin(reinterpret_cast<int*>(out_dist) + b * S_ + tid, v);
            sdmin[tid] = 0x7F800000;
            __threadfence();   // publish this thread's atomicMin before count
        }
        __syncthreads();
        if (tid == 0) {
            const unsigned int old = atomicAdd(&g_cnt[b], 1u);
            s_run = ((old & (TPB - 1u)) == (TPB - 1u)) ? 1 : 0;
        }
        __syncthreads();
        if (s_run) {
            __threadfence();   // acquire side
            mlp_tail(b, out_dist, W1, b1, W2, b2, out_cls, hs);
        }
    }
}

// ---------------------------------------------------------------------------
extern "C" void kernel_launch(void* const* d_in, const int* in_sizes, int n_in,
                              void* d_out, int out_size)
{
    const float* x  = (const float*)d_in[0];
    const float* sh = (const float*)d_in[1];
    const float* W1 = (const float*)d_in[2];
    const float* b1 = (const float*)d_in[3];
    const float* W2 = (const float*)d_in[4];
    const float* b2 = (const float*)d_in[5];

    float* out_dist = (float*)d_out;
    float* out_cls  = (float*)d_out + B_ * S_;

    // init distances to a huge positive sentinel (0x7f7f7f7f ~ 3.39e38)
    cudaMemsetAsync(out_dist, 0x7f, B_ * S_ * sizeof(float), 0);

    dist_kernel<<<GRID, THR>>>(x, sh, W1, b1, W2, b2, out_dist, out_cls);
}

// round 16
// speedup vs baseline: 5.7143x; 5.7143x over previous
#include <cuda_runtime.h>
#include <cuda_fp16.h>
#include <cstdint>

// ---------------------------------------------------------------------------
// Problem constants
// ---------------------------------------------------------------------------
#define B_  32
#define D_  3
#define T_  16384
#define S_  128
#define L_  16
#define H_  512
#define C_  10
#define TP  16369          // T - L + 1 valid positions
#define SHN 48             // D*L = K (3 k-steps of 16)

#define NT      128        // positions per block tile (GEMM N-tile)
#define NTILES  (B_ * (T_ / NT))   // 4096
#define THR     256
#define GRID    296        // 2 blocks / SM
#define XT_W    (NT + L_)  // 144 elements per x row in tile
#define LD4     ((D_ * XT_W) / 4)  // 108 float4 loads per tile

#define INF_F __int_as_float(0x7F800000)

// ---------------------------------------------------------------------------
// D(16x8) += A(16x16,row) * B(16x8,col)   f16 x f16 -> f32
__device__ __forceinline__ void mma16(float* d, uint32_t a0, uint32_t a1,
                                      uint32_t a2, uint32_t a3,
                                      uint32_t b0, uint32_t b1) {
    asm volatile(
        "mma.sync.aligned.m16n8k16.row.col.f32.f16.f16.f32 "
        "{%0,%1,%2,%3}, {%4,%5,%6,%7}, {%8,%9}, {%0,%1,%2,%3};"
        : "+f"(d[0]), "+f"(d[1]), "+f"(d[2]), "+f"(d[3])
        : "r"(a0), "r"(a1), "r"(a2), "r"(a3), "r"(b0), "r"(b1));
}

__device__ __forceinline__ uint32_t packh2(float lo, float hi) {
    __half2 h = __floats2half2_rn(lo, hi);
    return *reinterpret_cast<uint32_t*>(&h);
}

// ---------------------------------------------------------------------------
// Kernel 1: persistent fp16-MMA shapelet distance (exact R7 structure)
// ---------------------------------------------------------------------------
__global__ __launch_bounds__(THR, 2) void dist_kernel(
    const float* __restrict__ x,
    const float* __restrict__ shg,
    float* __restrict__ out_dist)
{
    __shared__ __align__(16) float  xs[D_ * XT_W];   // raw fp32 (exact wsq)
    __shared__ __align__(16) __half hA[D_ * XT_W];   // hA[i] = f16(x[i])
    __shared__ __align__(16) __half hB[D_ * XT_W];   // hB[i] = f16(x[i+1] in-row)
    __shared__ __align__(16) float  swsq[NT];
    __shared__ float  sssq[S_];
    __shared__ int    sdmin[S_];

    const int tid  = threadIdx.x;
    const int wid  = tid >> 5;
    const int lane = tid & 31;
    const int q    = lane >> 2;      // groupID
    const int r    = lane & 3;       // threadID_in_group

    const int mbase = (wid & 3) * 32;       // warp's 32 M-rows
    const int nbase = (wid >> 2) * 64;      // warp's 64 N-cols

    // --- one-time: exact fp32 shapelet squared norms; A fragments -> regs ---
    if (tid < S_) {
        const float* srow = shg + tid * SHN;
        float ssq = 0.f;
        #pragma unroll
        for (int k = 0; k < SHN; ++k) ssq = fmaf(srow[k], srow[k], ssq);
        sssq[tid] = ssq;
        sdmin[tid] = 0x7F800000;
    }

    // A fragments: afr[ks][mt][4]; tile-invariant
    uint32_t afr[3][2][4];
    #pragma unroll
    for (int ks = 0; ks < 3; ++ks) {
        #pragma unroll
        for (int mt = 0; mt < 2; ++mt) {
            const int r0 = mbase + mt * 16 + q;       // row for a0/a2
            const int r1 = r0 + 8;                    // row for a1/a3
            const int k0 = ks * 16 + 2 * r;
            const float* p0 = shg + r0 * SHN + k0;
            const float* p1 = shg + r1 * SHN + k0;
            afr[ks][mt][0] = packh2(-2.f * p0[0], -2.f * p0[1]);
            afr[ks][mt][1] = packh2(-2.f * p1[0], -2.f * p1[1]);
            afr[ks][mt][2] = packh2(-2.f * p0[8], -2.f * p0[9]);
            afr[ks][mt][3] = packh2(-2.f * p1[8], -2.f * p1[9]);
        }
    }
    __syncthreads();

    const uint32_t* hA32 = reinterpret_cast<const uint32_t*>(hA);
    const uint32_t* hB32 = reinterpret_cast<const uint32_t*>(hB);
    const uint32_t* hw = (q & 1) ? hB32 : hA32;
    const int lane_off = q + 2 * r - (q & 1);

    for (int tile = blockIdx.x; tile < NTILES; tile += GRID) {
        const int b     = tile >> 7;                  // 128 tiles / batch
        const int tbase = (tile & 127) * NT;
        const float* xb = x + (size_t)b * D_ * T_;

        // ---- phase 1: load x tile (fp32 + two fp16 copies) ----
        if (tid < LD4) {
            const int d = tid / (XT_W / 4);           // XT_W/4 = 36
            const int j = (tid % (XT_W / 4)) * 4;
            const int g = tbase + j;
            float4 v;
            if (g + 3 < T_) {
                v = *reinterpret_cast<const float4*>(xb + d * T_ + g);
            } else {
                v.x = (g     < T_) ? xb[d*T_ + g]     : 0.f;
                v.y = (g + 1 < T_) ? xb[d*T_ + g + 1] : 0.f;
                v.z = (g + 2 < T_) ? xb[d*T_ + g + 2] : 0.f;
                v.w = (g + 3 < T_) ? xb[d*T_ + g + 3] : 0.f;
            }
            *reinterpret_cast<float4*>(&xs[d * XT_W + j]) = v;
            const int hi = d * XT_W + j;
            *reinterpret_cast<uint32_t*>(&hA[hi])     = packh2(v.x, v.y);
            *reinterpret_cast<uint32_t*>(&hA[hi + 2]) = packh2(v.z, v.w);
            if (j > 0) hB[hi - 1] = __float2half(v.x);
            hB[hi    ] = __float2half(v.y);
            hB[hi + 1] = __float2half(v.z);
            hB[hi + 2] = __float2half(v.w);
        }
        __syncthreads();

        // ---- phase 2: wsq, one position per thread (tid < 128) ----
        if (tid < NT) {
            float w0 = 0.f, w1 = 0.f, w2 = 0.f;
            #pragma unroll
            for (int l = 0; l < L_; ++l) {
                const float v0 = xs[0 * XT_W + tid + l];
                const float v1 = xs[1 * XT_W + tid + l];
                const float v2 = xs[2 * XT_W + tid + l];
                w0 = fmaf(v0, v0, w0);
                w1 = fmaf(v1, v1, w1);
                w2 = fmaf(v2, v2, w2);
            }
            swsq[tid] = (tbase + tid < TP) ? (w0 + w1 + w2) : INF_F;
        }

        // ---- phase 3: MMA, warp tile 32M x 64N, K=48 (3 k-steps) ----
        float acc[2][8][4];
        #pragma unroll
        for (int mt = 0; mt < 2; ++mt)
            #pragma unroll
            for (int nt = 0; nt < 8; ++nt)
                #pragma unroll
                for (int e = 0; e < 4; ++e) acc[mt][nt][e] = 0.f;

        #pragma unroll
        for (int ks = 0; ks < 3; ++ks) {
            const int base = (ks * XT_W + nbase + lane_off) >> 1;
            #pragma unroll
            for (int nt = 0; nt < 8; ++nt) {
                const uint32_t b0 = hw[base + nt * 4];
                const uint32_t b1 = hw[base + nt * 4 + 4];
                mma16(acc[0][nt], afr[ks][0][0], afr[ks][0][1],
                                  afr[ks][0][2], afr[ks][0][3], b0, b1);
                mma16(acc[1][nt], afr[ks][1][0], afr[ks][1][1],
                                  afr[ks][1][2], afr[ks][1][3], b0, b1);
            }
        }
        __syncthreads();   // swsq ready

        // ---- phase 4: dist = min_n(acc + wsq[n]); smem atomic min ----
        float wq[8][2];
        #pragma unroll
        for (int nt = 0; nt < 8; ++nt) {
            wq[nt][0] = swsq[nbase + nt * 8 + r * 2    ];
            wq[nt][1] = swsq[nbase + nt * 8 + r * 2 + 1];
        }
        float rmin[2][2];
        #pragma unroll
        for (int mt = 0; mt < 2; ++mt)
            #pragma unroll
            for (int h = 0; h < 2; ++h) {
                float m = INF_F;
                #pragma unroll
                for (int nt = 0; nt < 8; ++nt) {
                    m = fminf(m, acc[mt][nt][h * 2    ] + wq[nt][0]);
                    m = fminf(m, acc[mt][nt][h * 2 + 1] + wq[nt][1]);
                }
                rmin[mt][h] = m;
            }
        #pragma unroll
        for (int mt = 0; mt < 2; ++mt)
            #pragma unroll
            for (int h = 0; h < 2; ++h) {
                float v = rmin[mt][h];
                v = fminf(v, __shfl_xor_sync(0xffffffffu, v, 1));
                v = fminf(v, __shfl_xor_sync(0xffffffffu, v, 2));
                rmin[mt][h] = v;
            }
        if (r == 0) {
            #pragma unroll
            for (int mt = 0; mt < 2; ++mt)
                #pragma unroll
                for (int h = 0; h < 2; ++h) {
                    const int row = mbase + mt * 16 + h * 8 + q;
                    const float v = rmin[mt][h] + sssq[row];
                    atomicMin(&sdmin[row], __float_as_int(v));
                }
        }
        __syncthreads();

        // ---- phase 5: fold into global; reset own slot ----
        if (tid < S_) {
            const int v = sdmin[tid];
            atomicMin(reinterpret_cast<int*>(out_dist) + b * S_ + tid, v);
            sdmin[tid] = 0x7F800000;
        }
    }
}

// ---------------------------------------------------------------------------
// Kernel 2: MLP — 8-deep load batching + interleaved shfl reductions
// ---------------------------------------------------------------------------
__global__ __launch_bounds__(512) void mlp_kernel(
    const float* __restrict__ dist,
    const float* __restrict__ W1,
    const float* __restrict__ b1,
    const float* __restrict__ W2,
    const float* __restrict__ b2,
    float* __restrict__ out_cls)
{
    __shared__ __align__(16) float4 ds4[S_ / 4];
    __shared__ __align__(16) float  hs[H_];
    const int b    = blockIdx.x;
    const int tid  = threadIdx.x;    // 512 threads = 16 warps
    const int warp = tid >> 5;
    const int lane = tid & 31;

    if (tid < S_ / 4)
        ds4[tid] = reinterpret_cast<const float4*>(dist + b * S_)[tid];
    __syncthreads();

    // Layer 1: warp w -> neurons [w*32, w*32+32), 8 per group (MLP=8).
    {
        const float4 d4 = ds4[lane];
        #pragma unroll 1
        for (int g = 0; g < 4; ++g) {
            // 8 coalesced row loads in flight
            float4 w4[8];
            #pragma unroll
            for (int j = 0; j < 8; ++j) {
                const int h = warp * 32 + g * 8 + j;
                w4[j] = __ldg(reinterpret_cast<const float4*>(W1 + h * S_) + lane);
            }
            // 8 independent dot partials
            float acc[8];
            #pragma unroll
            for (int j = 0; j < 8; ++j) {
                float a = d4.x * w4[j].x;
                a = fmaf(d4.y, w4[j].y, a);
                a = fmaf(d4.z, w4[j].z, a);
                a = fmaf(d4.w, w4[j].w, a);
                acc[j] = a;
            }
            // interleaved reduction: 5 levels x 8 independent shfls
            #pragma unroll
            for (int off = 16; off > 0; off >>= 1)
                #pragma unroll
                for (int j = 0; j < 8; ++j)
                    acc[j] += __shfl_xor_sync(0xffffffffu, acc[j], off);
            if (lane == 0) {
                #pragma unroll
                for (int j = 0; j < 8; ++j) {
                    const int h = warp * 32 + g * 8 + j;
                    hs[h] = fmaxf(acc[j] + b1[h], 0.f);
                }
            }
        }
    }
    __syncthreads();

    // Layer 2: warp w (< 10) computes class w
    if (warp < C_) {
        const float4* w4p = reinterpret_cast<const float4*>(W2 + warp * H_);
        const float4* h4p = reinterpret_cast<const float4*>(hs);
        float acc = 0.f;
        #pragma unroll
        for (int j = 0; j < H_ / (32 * 4); ++j) {
            const float4 w4 = __ldg(w4p + lane + j * 32);
            const float4 h4 = h4p[lane + j * 32];
            acc = fmaf(w4.x, h4.x, acc);
            acc = fmaf(w4.y, h4.y, acc);
            acc = fmaf(w4.z, h4.z, acc);
            acc = fmaf(w4.w, h4.w, acc);
        }
        #pragma unroll
        for (int off = 16; off > 0; off >>= 1)
            acc += __shfl_xor_sync(0xffffffffu, acc, off);
        if (lane == 0) out_cls[b * C_ + warp] = acc + b2[warp];
    }
}

// ---------------------------------------------------------------------------
extern "C" void kernel_launch(void* const* d_in, const int* in_sizes, int n_in,
                              void* d_out, int out_size)
{
    const float* x  = (const float*)d_in[0];
    const float* sh = (const float*)d_in[1];
    const float* W1 = (const float*)d_in[2];
    const float* b1 = (const float*)d_in[3];
    const float* W2 = (const float*)d_in[4];
    const float* b2 = (const float*)d_in[5];

    float* out_dist = (float*)d_out;
    float* out_cls  = (float*)d_out + B_ * S_;

    // init distances to a huge positive sentinel (0x7f7f7f7f ~ 3.39e38)
    cudaMemsetAsync(out_dist, 0x7f, B_ * S_ * sizeof(float), 0);

    dist_kernel<<<GRID, THR>>>(x, sh, out_dist);
    mlp_kernel<<<B_, 512>>>(out_dist, W1, b1, W2, b2, out_cls);
}

// round 17
// speedup vs baseline: 5.7534x; 1.0068x over previous
#include <cuda_runtime.h>
#include <cuda_fp16.h>
#include <cstdint>

// ---------------------------------------------------------------------------
// Problem constants
// ---------------------------------------------------------------------------
#define B_  32
#define D_  3
#define T_  16384
#define S_  128
#define L_  16
#define H_  512
#define C_  10
#define TP  16369          // T - L + 1 valid positions
#define SHN 48             // D*L = K (3 k-steps of 16)

#define NT      128        // positions per block tile (GEMM N-tile)
#define TPB     (T_ / NT)          // 128 tiles per batch
#define NTILES  (B_ * TPB)         // 4096
#define THR     256
#define GRID    296        // 2 blocks / SM
#define XT_W    (NT + L_)  // 144 elements per x row in tile
#define LD4     ((D_ * XT_W) / 4)  // 108 float4 loads per tile

#define INF_F __int_as_float(0x7F800000)

// ---------------------------------------------------------------------------
// D(16x8) += A(16x16,row) * B(16x8,col)   f16 x f16 -> f32
__device__ __forceinline__ void mma16(float* d, uint32_t a0, uint32_t a1,
                                      uint32_t a2, uint32_t a3,
                                      uint32_t b0, uint32_t b1) {
    asm volatile(
        "mma.sync.aligned.m16n8k16.row.col.f32.f16.f16.f32 "
        "{%0,%1,%2,%3}, {%4,%5,%6,%7}, {%8,%9}, {%0,%1,%2,%3};"
        : "+f"(d[0]), "+f"(d[1]), "+f"(d[2]), "+f"(d[3])
        : "r"(a0), "r"(a1), "r"(a2), "r"(a3), "r"(b0), "r"(b1));
}

__device__ __forceinline__ uint32_t packh2(float lo, float hi) {
    __half2 h = __floats2half2_rn(lo, hi);
    return *reinterpret_cast<uint32_t*>(&h);
}

// ---------------------------------------------------------------------------
// Kernel 1: persistent fp16-MMA shapelet distance
//   batch-contiguous tile chunks; min accumulated in registers; flushed at
//   batch boundaries only (removes per-tile barrier + atomic traffic)
// ---------------------------------------------------------------------------
__global__ __launch_bounds__(THR, 2) void dist_kernel(
    const float* __restrict__ x,
    const float* __restrict__ shg,
    float* __restrict__ out_dist)
{
    __shared__ __align__(16) float  xs[D_ * XT_W];   // raw fp32 (exact wsq)
    __shared__ __align__(16) __half hA[D_ * XT_W];   // hA[i] = f16(x[i])
    __shared__ __align__(16) __half hB[D_ * XT_W];   // hB[i] = f16(x[i+1] in-row)
    __shared__ __align__(16) float  swsq[NT];
    __shared__ float  sssq[S_];
    __shared__ int    sdmin[S_];

    const int tid  = threadIdx.x;
    const int wid  = tid >> 5;
    const int lane = tid & 31;
    const int q    = lane >> 2;      // groupID
    const int r    = lane & 3;       // threadID_in_group

    const int mbase = (wid & 3) * 32;       // warp's 32 M-rows
    const int nbase = (wid >> 2) * 64;      // warp's 64 N-cols

    // --- one-time: exact fp32 shapelet squared norms; A fragments -> regs ---
    if (tid < S_) {
        const float* srow = shg + tid * SHN;
        float ssq = 0.f;
        #pragma unroll
        for (int k = 0; k < SHN; ++k) ssq = fmaf(srow[k], srow[k], ssq);
        sssq[tid] = ssq;
        sdmin[tid] = 0x7F800000;
    }

    // A fragments: afr[ks][mt][4]; tile-invariant
    uint32_t afr[3][2][4];
    #pragma unroll
    for (int ks = 0; ks < 3; ++ks) {
        #pragma unroll
        for (int mt = 0; mt < 2; ++mt) {
            const int r0 = mbase + mt * 16 + q;       // row for a0/a2
            const int r1 = r0 + 8;                    // row for a1/a3
            const int k0 = ks * 16 + 2 * r;
            const float* p0 = shg + r0 * SHN + k0;
            const float* p1 = shg + r1 * SHN + k0;
            afr[ks][mt][0] = packh2(-2.f * p0[0], -2.f * p0[1]);
            afr[ks][mt][1] = packh2(-2.f * p1[0], -2.f * p1[1]);
            afr[ks][mt][2] = packh2(-2.f * p0[8], -2.f * p0[9]);
            afr[ks][mt][3] = packh2(-2.f * p1[8], -2.f * p1[9]);
        }
    }
    __syncthreads();

    const uint32_t* hA32 = reinterpret_cast<const uint32_t*>(hA);
    const uint32_t* hB32 = reinterpret_cast<const uint32_t*>(hB);
    const uint32_t* hw = (q & 1) ? hB32 : hA32;
    const int lane_off = q + 2 * r - (q & 1);

    // flush accumulated rmin for batch fb into global (block-uniform call)
    auto flush = [&](int fb, float rmin[2][2]) {
        #pragma unroll
        for (int mt = 0; mt < 2; ++mt)
            #pragma unroll
            for (int h = 0; h < 2; ++h) {
                float v = rmin[mt][h];
                v = fminf(v, __shfl_xor_sync(0xffffffffu, v, 1));
                v = fminf(v, __shfl_xor_sync(0xffffffffu, v, 2));
                rmin[mt][h] = v;
            }
        if (r == 0) {
            #pragma unroll
            for (int mt = 0; mt < 2; ++mt)
                #pragma unroll
                for (int h = 0; h < 2; ++h) {
                    const int row = mbase + mt * 16 + h * 8 + q;
                    const float v = rmin[mt][h] + sssq[row];
                    atomicMin(&sdmin[row], __float_as_int(v));
                }
        }
        __syncthreads();
        if (tid < S_) {
            atomicMin(reinterpret_cast<int*>(out_dist) + fb * S_ + tid,
                      sdmin[tid]);
            sdmin[tid] = 0x7F800000;
        }
        __syncthreads();
    };

    // batch-contiguous chunk for this block (13-14 tiles, <=1 batch crossing)
    const int start = (int)(((long long)blockIdx.x * NTILES) / GRID);
    const int stop  = (int)(((long long)(blockIdx.x + 1) * NTILES) / GRID);

    float rmin[2][2];
    #pragma unroll
    for (int mt = 0; mt < 2; ++mt)
        #pragma unroll
        for (int h = 0; h < 2; ++h) rmin[mt][h] = INF_F;

    int cur_b = start >> 7;     // TPB = 128

    for (int tile = start; tile < stop; ++tile) {
        const int b = tile >> 7;
        if (b != cur_b) {       // batch boundary: flush + reset (block-uniform)
            flush(cur_b, rmin);
            #pragma unroll
            for (int mt = 0; mt < 2; ++mt)
                #pragma unroll
                for (int h = 0; h < 2; ++h) rmin[mt][h] = INF_F;
            cur_b = b;
        }

        const int tbase = (tile & (TPB - 1)) * NT;
        const float* xb = x + (size_t)b * D_ * T_;

        // ---- phase 1: load x tile (fp32 + two fp16 copies) ----
        if (tid < LD4) {
            const int d = tid / (XT_W / 4);           // XT_W/4 = 36
            const int j = (tid % (XT_W / 4)) * 4;
            const int g = tbase + j;
            float4 v;
            if (g + 3 < T_) {
                v = *reinterpret_cast<const float4*>(xb + d * T_ + g);
            } else {
                v.x = (g     < T_) ? xb[d*T_ + g]     : 0.f;
                v.y = (g + 1 < T_) ? xb[d*T_ + g + 1] : 0.f;
                v.z = (g + 2 < T_) ? xb[d*T_ + g + 2] : 0.f;
                v.w = (g + 3 < T_) ? xb[d*T_ + g + 3] : 0.f;
            }
            *reinterpret_cast<float4*>(&xs[d * XT_W + j]) = v;
            const int hi = d * XT_W + j;
            *reinterpret_cast<uint32_t*>(&hA[hi])     = packh2(v.x, v.y);
            *reinterpret_cast<uint32_t*>(&hA[hi + 2]) = packh2(v.z, v.w);
            if (j > 0) hB[hi - 1] = __float2half(v.x);
            hB[hi    ] = __float2half(v.y);
            hB[hi + 1] = __float2half(v.z);
            hB[hi + 2] = __float2half(v.w);
        }
        __syncthreads();

        // ---- phase 2: wsq, one position per thread (tid < 128) ----
        if (tid < NT) {
            float w0 = 0.f, w1 = 0.f, w2 = 0.f;
            #pragma unroll
            for (int l = 0; l < L_; ++l) {
                const float v0 = xs[0 * XT_W + tid + l];
                const float v1 = xs[1 * XT_W + tid + l];
                const float v2 = xs[2 * XT_W + tid + l];
                w0 = fmaf(v0, v0, w0);
                w1 = fmaf(v1, v1, w1);
                w2 = fmaf(v2, v2, w2);
            }
            swsq[tid] = (tbase + tid < TP) ? (w0 + w1 + w2) : INF_F;
        }

        // ---- phase 3: MMA, warp tile 32M x 64N, K=48 (3 k-steps) ----
        float acc[2][8][4];
        #pragma unroll
        for (int mt = 0; mt < 2; ++mt)
            #pragma unroll
            for (int nt = 0; nt < 8; ++nt)
                #pragma unroll
                for (int e = 0; e < 4; ++e) acc[mt][nt][e] = 0.f;

        #pragma unroll
        for (int ks = 0; ks < 3; ++ks) {
            const int base = (ks * XT_W + nbase + lane_off) >> 1;
            #pragma unroll
            for (int nt = 0; nt < 8; ++nt) {
                const uint32_t b0 = hw[base + nt * 4];
                const uint32_t b1 = hw[base + nt * 4 + 4];
                mma16(acc[0][nt], afr[ks][0][0], afr[ks][0][1],
                                  afr[ks][0][2], afr[ks][0][3], b0, b1);
                mma16(acc[1][nt], afr[ks][1][0], afr[ks][1][1],
                                  afr[ks][1][2], afr[ks][1][3], b0, b1);
            }
        }
        __syncthreads();   // swsq ready; all smem reads of this tile complete

        // ---- phase 4: accumulate min into registers (no barriers/atomics) ----
        // (safe vs next tile's writes: every warp passes the next phase-1
        //  barrier only after finishing its own phase 4)
        float wq[8][2];
        #pragma unroll
        for (int nt = 0; nt < 8; ++nt) {
            wq[nt][0] = swsq[nbase + nt * 8 + r * 2    ];
            wq[nt][1] = swsq[nbase + nt * 8 + r * 2 + 1];
        }
        #pragma unroll
        for (int mt = 0; mt < 2; ++mt)
            #pragma unroll
            for (int h = 0; h < 2; ++h) {
                float m = rmin[mt][h];
                #pragma unroll
                for (int nt = 0; nt < 8; ++nt) {
                    m = fminf(m, acc[mt][nt][h * 2    ] + wq[nt][0]);
                    m = fminf(m, acc[mt][nt][h * 2 + 1] + wq[nt][1]);
                }
                rmin[mt][h] = m;
            }
    }

    flush(cur_b, rmin);
}

// ---------------------------------------------------------------------------
// Kernel 2: MLP — 8-deep load batching + interleaved shfl reductions
// ---------------------------------------------------------------------------
__global__ __launch_bounds__(512) void mlp_kernel(
    const float* __restrict__ dist,
    const float* __restrict__ W1,
    const float* __restrict__ b1,
    const float* __restrict__ W2,
    const float* __restrict__ b2,
    float* __restrict__ out_cls)
{
    __shared__ __align__(16) float4 ds4[S_ / 4];
    __shared__ __align__(16) float  hs[H_];
    const int b    = blockIdx.x;
    const int tid  = threadIdx.x;    // 512 threads = 16 warps
    const int warp = tid >> 5;
    const int lane = tid & 31;

    if (tid < S_ / 4)
        ds4[tid] = reinterpret_cast<const float4*>(dist + b * S_)[tid];
    __syncthreads();

    // Layer 1: warp w -> neurons [w*32, w*32+32), 8 per group (MLP=8)
    {
        const float4 d4 = ds4[lane];
        #pragma unroll 1
        for (int g = 0; g < 4; ++g) {
            float4 w4[8];
            #pragma unroll
            for (int j = 0; j < 8; ++j) {
                const int h = warp * 32 + g * 8 + j;
                w4[j] = __ldg(reinterpret_cast<const float4*>(W1 + h * S_) + lane);
            }
            float acc[8];
            #pragma unroll
            for (int j = 0; j < 8; ++j) {
                float a = d4.x * w4[j].x;
                a = fmaf(d4.y, w4[j].y, a);
                a = fmaf(d4.z, w4[j].z, a);
                a = fmaf(d4.w, w4[j].w, a);
                acc[j] = a;
            }
            #pragma unroll
            for (int off = 16; off > 0; off >>= 1)
                #pragma unroll
                for (int j = 0; j < 8; ++j)
                    acc[j] += __shfl_xor_sync(0xffffffffu, acc[j], off);
            if (lane == 0) {
                #pragma unroll
                for (int j = 0; j < 8; ++j) {
                    const int h = warp * 32 + g * 8 + j;
                    hs[h] = fmaxf(acc[j] + b1[h], 0.f);
                }
            }
        }
    }
    __syncthreads();

    // Layer 2: warp w (< 10) computes class w
    if (warp < C_) {
        const float4* w4p = reinterpret_cast<const float4*>(W2 + warp * H_);
        const float4* h4p = reinterpret_cast<const float4*>(hs);
        float acc = 0.f;
        #pragma unroll
        for (int j = 0; j < H_ / (32 * 4); ++j) {
            const float4 w4 = __ldg(w4p + lane + j * 32);
            const float4 h4 = h4p[lane + j * 32];
            acc = fmaf(w4.x, h4.x, acc);
            acc = fmaf(w4.y, h4.y, acc);
            acc = fmaf(w4.z, h4.z, acc);
            acc = fmaf(w4.w, h4.w, acc);
        }
        #pragma unroll
        for (int off = 16; off > 0; off >>= 1)
            acc += __shfl_xor_sync(0xffffffffu, acc, off);
        if (lane == 0) out_cls[b * C_ + warp] = acc + b2[warp];
    }
}

// ---------------------------------------------------------------------------
extern "C" void kernel_launch(void* const* d_in, const int* in_sizes, int n_in,
                              void* d_out, int out_size)
{
    const float* x  = (const float*)d_in[0];
    const float* sh = (const float*)d_in[1];
    const float* W1 = (const float*)d_in[2];
    const float* b1 = (const float*)d_in[3];
    const float* W2 = (const float*)d_in[4];
    const float* b2 = (const float*)d_in[5];

    float* out_dist = (float*)d_out;
    float* out_cls  = (float*)d_out + B_ * S_;

    // init distances to a huge positive sentinel (0x7f7f7f7f ~ 3.39e38)
    cudaMemsetAsync(out_dist, 0x7f, B_ * S_ * sizeof(float), 0);

    dist_kernel<<<GRID, THR>>>(x, sh, out_dist);
    mlp_kernel<<<B_, 512>>>(out_dist, W1, b1, W2, b2, out_cls);
}